// round 5
// baseline (speedup 1.0000x reference)
#include <cuda_runtime.h>
#include <cuda_bf16.h>

#define T 256
#define H 1024
#define E 64
#define IDIM 512
#define SI 2048
#define TOPK 6

// ---------------- device scratch ----------------
__device__ int   g_cnt[E];
__device__ int   g_slot[E * T];
__device__ int   g_tok[E * T];
__device__ float g_wt[E * T];
__device__ float g_act[T * TOPK * IDIM];   // 3 MB
__device__ float g_eo[T * TOPK * H];       // 6 MB
__device__ float g_sact[T * SI];           // 2 MB

__device__ __forceinline__ float silu(float v) { return v / (1.0f + expf(-v)); }

// ---------------- init ----------------
__global__ void init_kernel() {
    if (threadIdx.x < E) g_cnt[threadIdx.x] = 0;
}

// ---------------- gate + routing: one block per token ----------------
__global__ void gate_routing_kernel(const float* __restrict__ x,
                                    const float* __restrict__ gw,
                                    const float* __restrict__ ebias) {
    __shared__ float xs[H];
    __shared__ float part[256];
    __shared__ float logits[E];
    int t = blockIdx.x, tid = threadIdx.x;

    ((float4*)xs)[tid] = ((const float4*)(x + (size_t)t * H))[tid];
    __syncthreads();

    int e = tid >> 2, q = tid & 3;
    const float* gr = gw + (size_t)e * H + q * 256;
    const float* xr = xs + q * 256;
    float s = 0.0f;
#pragma unroll 8
    for (int k = 0; k < 256; k += 4) {
        float4 g = *(const float4*)(gr + k);
        float4 xv = *(const float4*)(xr + k);
        s += g.x * xv.x + g.y * xv.y + g.z * xv.z + g.w * xv.w;
    }
    part[tid] = s;
    __syncthreads();
    if (tid < E) logits[tid] = part[tid * 4] + part[tid * 4 + 1] + part[tid * 4 + 2] + part[tid * 4 + 3];
    __syncthreads();

    if (tid == 0) {
        float sc[E], swb[E];
        for (int i = 0; i < E; i++) {
            float l = logits[i];
            sc[i] = 1.0f / (1.0f + expf(-l));
            swb[i] = sc[i] + ebias[i];
        }
        float gs[8];
        for (int g = 0; g < 8; g++) {
            float m1 = -1e30f, m2 = -1e30f;
            for (int j = 0; j < 8; j++) {
                float v = swb[g * 8 + j];
                if (v > m1) { m2 = m1; m1 = v; }
                else if (v > m2) { m2 = v; }
            }
            gs[g] = m1 + m2;
        }
        bool gsel[8];
        for (int g = 0; g < 8; g++) gsel[g] = false;
        for (int r = 0; r < 4; r++) {
            int best = 0; float bv = -1e30f;
            for (int g = 0; g < 8; g++)
                if (!gsel[g] && gs[g] > bv) { bv = gs[g]; best = g; }
            gsel[best] = true;
        }
        bool picked[E];
        for (int i = 0; i < E; i++) picked[i] = false;
        int idx[TOPK];
        float wsum = 0.0f;
        for (int r = 0; r < TOPK; r++) {
            int best = 0; float bv = -1e30f;
            for (int i = 0; i < E; i++) {
                if (picked[i]) continue;
                float v = gsel[i >> 3] ? swb[i] : 0.0f;
                if (v > bv) { bv = v; best = i; }
            }
            picked[best] = true;
            idx[r] = best;
            wsum += sc[best];
        }
        float inv = 2.5f / (wsum + 1e-20f);
        for (int r = 0; r < TOPK; r++) {
            int ee = idx[r];
            int pos = atomicAdd(&g_cnt[ee], 1);
            g_slot[ee * T + pos] = t * TOPK + r;
            g_tok[ee * T + pos] = t;
            g_wt[ee * T + pos] = sc[ee] * inv;
        }
    }
}

// ================= register-direct bf16-split MMA GEMM =================
// C[M=32, N=64] = A[32, KD] * B[N, KD]^T. fp32 operands loaded from gmem
// DIRECTLY in m16n8k16 fragment layout (no smem staging, no barriers in the
// mainloop), split in registers into bf16 hi (truncation) + lo (residual),
// 3-term MMA: hi*hi + hi*lo + lo*hi. Dropped lo*lo term ~2^-16 relative.
// 128 threads = 4 warps: warp (wm, wn) owns m16 x n32.

__device__ __forceinline__ void mma_bf16(float c[4], const unsigned a[4],
                                         unsigned b0, unsigned b1) {
    asm("mma.sync.aligned.m16n8k16.row.col.f32.bf16.bf16.f32 "
        "{%0,%1,%2,%3}, {%4,%5,%6,%7}, {%8,%9}, {%0,%1,%2,%3};"
        : "+f"(c[0]), "+f"(c[1]), "+f"(c[2]), "+f"(c[3])
        : "r"(a[0]), "r"(a[1]), "r"(a[2]), "r"(a[3]), "r"(b0), "r"(b1));
}

// split two fp32 into packed bf16x2 hi (truncate) and lo (residual, rn)
__device__ __forceinline__ void split_pair(float2 v, unsigned &hi, unsigned &lo) {
    unsigned ux = __float_as_uint(v.x), uy = __float_as_uint(v.y);
    float lx = v.x - __uint_as_float(ux & 0xffff0000u);
    float ly = v.y - __uint_as_float(uy & 0xffff0000u);
    asm("prmt.b32 %0, %1, %2, 0x7632;" : "=r"(hi) : "r"(ux), "r"(uy));
    __nv_bfloat162 l2 = __floats2bfloat162_rn(lx, ly);
    lo = *reinterpret_cast<unsigned*>(&l2);
}

// EPI: 0 = silu(acc0)*acc1   1 = acc0 * combine_weight   2 = plain acc0
template<int KD, bool TWOB, int EPI, bool GATHER, bool ATOK, int ASRC, int ODST>
__device__ __forceinline__ void gemm_body(
    int bx, int by, int bz,
    const float* __restrict__ Ain, const float* __restrict__ B1in,
    const float* __restrict__ B2in, float* __restrict__ Oout,
    int ostride, long estrideB)
{
    constexpr int NB = TWOB ? 2 : 1;

    const float* A = (ASRC == 0) ? Ain : (ASRC == 1) ? (const float*)g_act : (const float*)g_sact;
    float* O = (ODST == 0) ? Oout : (ODST == 1) ? g_act : (ODST == 2) ? g_eo : g_sact;

    int tid = threadIdx.x, lane = tid & 31, wid = tid >> 5;
    int wm = wid & 1, wn = wid >> 1;
    int n0 = bx * 64;

    __shared__ int s_row[32];
    __shared__ int s_orow[32];
    __shared__ float s_wt[32];

    int mcnt = 32;
    const float* Bp[NB];
    if (GATHER) {
        int e = by;
        int n = g_cnt[e];
        int m0 = bz * 32;
        if (m0 >= n) return;
        mcnt = min(32, n - m0);
        if (tid < 32) {
            bool v = tid < mcnt;
            int idx = e * T + m0 + tid;
            s_row[tid]  = v ? (ATOK ? g_tok[idx] : g_slot[idx]) : 0;
            s_orow[tid] = v ? g_slot[idx] : 0;
            s_wt[tid]   = v ? g_wt[idx] : 0.0f;
        }
        Bp[0] = B1in + (size_t)e * estrideB + (size_t)n0 * KD;
        if (TWOB) Bp[1] = B2in + (size_t)e * estrideB + (size_t)n0 * KD;
    } else {
        int m0 = by * 32;
        if (tid < 32) { s_row[tid] = m0 + tid; s_orow[tid] = m0 + tid; }
        Bp[0] = B1in + (size_t)n0 * KD;
        if (TWOB) Bp[1] = B2in + (size_t)n0 * KD;
    }
    __syncthreads();

    int g = lane >> 2, c0 = (lane & 3) * 2;

    // fragment-order gmem pointers
    const float* pa0 = A + (size_t)s_row[wm * 16 + g] * KD + c0;
    const float* pa1 = A + (size_t)s_row[wm * 16 + g + 8] * KD + c0;
    const float* pb[NB][4];
#pragma unroll
    for (int m = 0; m < NB; m++)
#pragma unroll
        for (int nt = 0; nt < 4; nt++)
            pb[m][nt] = Bp[m] + (size_t)(wn * 32 + nt * 8 + g) * KD + c0;

    float acc[NB][4][4];
#pragma unroll
    for (int m = 0; m < NB; m++)
#pragma unroll
        for (int nt = 0; nt < 4; nt++)
#pragma unroll
            for (int j = 0; j < 4; j++) acc[m][nt][j] = 0.0f;

    // register double-buffer: two k16 steps in flight
    float2 fa[2][4];
    float2 fb[2][NB][4][2];

    auto load_step = [&](int buf, int k) {
        fa[buf][0] = *(const float2*)(pa0 + k);        // (row g,   k0)
        fa[buf][1] = *(const float2*)(pa1 + k);        // (row g+8, k0)
        fa[buf][2] = *(const float2*)(pa0 + k + 8);    // (row g,   k0+8)
        fa[buf][3] = *(const float2*)(pa1 + k + 8);    // (row g+8, k0+8)
#pragma unroll
        for (int m = 0; m < NB; m++)
#pragma unroll
            for (int nt = 0; nt < 4; nt++) {
                fb[buf][m][nt][0] = *(const float2*)(pb[m][nt] + k);
                fb[buf][m][nt][1] = *(const float2*)(pb[m][nt] + k + 8);
            }
    };

    auto compute_step = [&](int buf) {
        unsigned ah[4], al[4];
#pragma unroll
        for (int i = 0; i < 4; i++) split_pair(fa[buf][i], ah[i], al[i]);
#pragma unroll
        for (int m = 0; m < NB; m++)
#pragma unroll
            for (int nt = 0; nt < 4; nt++) {
                unsigned bh0, bl0, bh1, bl1;
                split_pair(fb[buf][m][nt][0], bh0, bl0);
                split_pair(fb[buf][m][nt][1], bh1, bl1);
                mma_bf16(acc[m][nt], ah, bh0, bh1);
                mma_bf16(acc[m][nt], ah, bl0, bl1);
                mma_bf16(acc[m][nt], al, bh0, bh1);
            }
    };

    load_step(0, 0);
#pragma unroll 1
    for (int k = 0; k < KD; k += 32) {
        load_step(1, k + 16);
        compute_step(0);
        if (k + 32 < KD) load_step(0, k + 32);
        compute_step(1);
    }

    // epilogue
    int tq = lane & 3;
#pragma unroll
    for (int half = 0; half < 2; half++) {
        int m = wm * 16 + g + half * 8;
        if (m >= mcnt) continue;
        float w = (EPI == 1) ? s_wt[m] : 0.0f;
        float* op = O + (size_t)s_orow[m] * ostride + n0 + wn * 32 + 2 * tq;
#pragma unroll
        for (int nt = 0; nt < 4; nt++) {
            float v0, v1;
            if (EPI == 0) {
                v0 = silu(acc[0][nt][half * 2])     * acc[1][nt][half * 2];
                v1 = silu(acc[0][nt][half * 2 + 1]) * acc[1][nt][half * 2 + 1];
            } else if (EPI == 1) {
                v0 = acc[0][nt][half * 2] * w;
                v1 = acc[0][nt][half * 2 + 1] * w;
            } else {
                v0 = acc[0][nt][half * 2];
                v1 = acc[0][nt][half * 2 + 1];
            }
            *(float2*)&op[nt * 8] = make_float2(v0, v1);
        }
    }
}

// ---- K1: sharedUp (256 blocks) + routed stageA (4096 blocks) ----
#define K1_SHARED 256
#define K1_TOTAL (K1_SHARED + 8 * 64 * 8)
__global__ __launch_bounds__(128) void k1_kernel(
    const float* __restrict__ x, const float* __restrict__ w1,
    const float* __restrict__ w3, const float* __restrict__ wsg,
    const float* __restrict__ wsu)
{
    int id = blockIdx.x;
    if (id < K1_SHARED) {
        // sact = silu(x @ wsg^T) * (x @ wsu^T)
        gemm_body<1024, true, 0, false, false, 0, 3>(
            id & 31, id >> 5, 0, x, wsg, wsu, nullptr, SI, 0);
    } else {
        int rid = id - K1_SHARED;
        // act = silu(x_e @ w1^T) * (x_e @ w3^T)  [gather tokens]
        gemm_body<1024, true, 0, true, true, 0, 1>(
            rid & 7, (rid >> 3) & 63, rid >> 9, x, w1, w3, nullptr,
            IDIM, (long)IDIM * H);
    }
}

// ---- K2: sharedDown (128 blocks) + routed stageB (8192 blocks) ----
#define K2_SHARED 128
#define K2_TOTAL (K2_SHARED + 16 * 64 * 8)
__global__ __launch_bounds__(128) void k2_kernel(
    const float* __restrict__ w2, const float* __restrict__ wsd,
    float* __restrict__ out)
{
    int id = blockIdx.x;
    if (id < K2_SHARED) {
        // out = sact @ wsd^T
        gemm_body<2048, false, 2, false, false, 2, 0>(
            id & 15, id >> 4, 0, nullptr, wsd, wsd, out, H, 0);
    } else {
        int rid = id - K2_SHARED;
        // eo = (act_e @ w2^T) * cw  [gather slots]
        gemm_body<512, false, 1, true, false, 1, 2>(
            rid & 15, (rid >> 4) & 63, rid >> 10, nullptr, w2, w2, nullptr,
            H, (long)H * IDIM);
    }
}

// ---- combine: out += sum of the 6 weighted expert outputs per token ----
__global__ void combine_kernel(float* __restrict__ out) {
    int idx = blockIdx.x * 256 + threadIdx.x;
    int t = idx >> 10;
    int h = idx & 1023;
    float s = out[idx];
#pragma unroll
    for (int k = 0; k < TOPK; k++)
        s += g_eo[((size_t)(t * TOPK + k) << 10) + h];
    out[idx] = s;
}

// ---------------- launch ----------------
extern "C" void kernel_launch(void* const* d_in, const int* in_sizes, int n_in,
                              void* d_out, int out_size) {
    const float* x     = (const float*)d_in[0];
    const float* gw    = (const float*)d_in[1];
    const float* ebias = (const float*)d_in[2];
    const float* w1    = (const float*)d_in[3];
    const float* w3    = (const float*)d_in[4];
    const float* w2    = (const float*)d_in[5];
    const float* wsg   = (const float*)d_in[6];
    const float* wsu   = (const float*)d_in[7];
    const float* wsd   = (const float*)d_in[8];
    float* out = (float*)d_out;

    init_kernel<<<1, 64>>>();
    gate_routing_kernel<<<T, 256>>>(x, gw, ebias);
    k1_kernel<<<K1_TOTAL, 128>>>(x, w1, w3, wsg, wsu);
    k2_kernel<<<K2_TOTAL, 128>>>(w2, wsd, out);
    combine_kernel<<<(T * H) / 256, 256>>>(out);
}